// round 8
// baseline (speedup 1.0000x reference)
#include <cuda_runtime.h>
#include <cuda_bf16.h>
#include <math.h>
#include <stdint.h>

#define NM 2
#define NB 32
#define NL 512
#define NS 26
#define NQ 512
#define HMM_EPS 1e-16f
#define NTOT (NM*NB*NL*NQ)   // 16,777,216

typedef unsigned long long ull;

// ---- scratch (no allocs allowed: __device__ globals) ----
__device__ __nv_bfloat16 g_Ah [NM*NQ*NQ]; // A  bf16 [m][k][q]  (fwd)
__device__ __nv_bfloat16 g_ATh[NM*NQ*NQ]; // A^T bf16 [m][k][j] (bwd)
__device__ float  g_Bt[NM*NS*NQ];         // B transposed [m][s][q]
__device__ float  g_init[NM*NQ];
__device__ float  g_E    [NTOT];          // em + eps (linear), [m][b][l][q]
__device__ float  g_alpha[NTOT];          // normalized linear alpha
__device__ float  g_beta [NTOT];          // normalized linear beta
__device__ float  g_Sa[NM*NB*NL];         // cumulative log-scale (fwd)
__device__ float  g_Sb[NM*NB*NL];         // cumulative log-scale (bwd)

// ---- packed f32x2 helpers ----
#define FMA2(d, a, b) asm("fma.rn.f32x2 %0, %1, %2, %0;" : "+l"(d) : "l"(a), "l"(b))

// two bf16 (packed in one u32, lo=q0 hi=q1) -> f32x2 pair (q0,q1)
__device__ __forceinline__ ull bf2f2(uint32_t w) {
    ull r;
    asm("mov.b64 %0, {%1, %2};" : "=l"(r) : "r"(w << 16), "r"(w & 0xFFFF0000u));
    return r;
}
__device__ __forceinline__ float2 lohi(ull p) {
    float lo, hi;
    asm("mov.b64 {%0, %1}, %2;" : "=f"(lo), "=f"(hi) : "l"(p));
    return make_float2(lo, hi);
}
// load float4 (v0,v0,v1,v1) from shared as two f32x2 operands
__device__ __forceinline__ void lds_y(uint32_t addr, ull& y0, ull& y1) {
    asm volatile("{\n\t.reg .b32 a,b,c,d;\n\t"
                 "ld.shared.v4.b32 {a,b,c,d}, [%2];\n\t"
                 "mov.b64 %0, {a,b};\n\t"
                 "mov.b64 %1, {c,d};\n\t}"
                 : "=l"(y0), "=l"(y1) : "r"(addr));
}
__device__ __forceinline__ uint32_t smem_u32(const void* p) {
    uint32_t a;
    asm("{ .reg .u64 t; cvta.to.shared.u64 t, %1; cvt.u32.u64 %0, t; }"
        : "=r"(a) : "l"(p));
    return a;
}

// ============================================================
// Prep: row softmax of transition (writes bf16 A and A^T) + init.
// ============================================================
__global__ void prep_rows_kernel(const float* __restrict__ trans,
                                 const float* __restrict__ initl) {
    int bid = blockIdx.x;
    int t = threadIdx.x;
    int lane = t & 31, warp = t >> 5;
    __shared__ float red[16];
    __shared__ float s_max, s_inv;

    const float* row;
    if (bid < NM*NQ) row = trans + (size_t)bid * NQ;
    else             row = initl + (size_t)(bid - NM*NQ) * NQ;
    float x = row[t];

    float v = x;
    #pragma unroll
    for (int o = 16; o; o >>= 1) v = fmaxf(v, __shfl_xor_sync(0xffffffffu, v, o));
    if (lane == 0) red[warp] = v;
    __syncthreads();
    if (t == 0) {
        float m = red[0];
        #pragma unroll
        for (int i = 1; i < 16; i++) m = fmaxf(m, red[i]);
        s_max = m;
    }
    __syncthreads();

    float e = expf(x - s_max);

    v = e;
    #pragma unroll
    for (int o = 16; o; o >>= 1) v += __shfl_xor_sync(0xffffffffu, v, o);
    if (lane == 0) red[warp] = v;
    __syncthreads();
    if (t == 0) {
        float s = 0.f;
        #pragma unroll
        for (int i = 0; i < 16; i++) s += red[i];
        s_inv = 1.0f / s;
    }
    __syncthreads();

    float p = e * s_inv;
    if (bid < NM*NQ) {
        int m = bid >> 9, r = bid & 511;
        __nv_bfloat16 h = __float2bfloat16(p);
        g_Ah [(size_t)bid * NQ + t] = h;
        g_ATh[((size_t)m * NQ + t) * NQ + r] = h;
    } else {
        g_init[(bid - NM*NQ) * NQ + t] = p;
    }
}

// ============================================================
// Prep: B = softmax(emission, axis=s), stored transposed [m][s][q].
// ============================================================
__global__ void prep_B_kernel(const float* __restrict__ emis) {
    int gw = (blockIdx.x * blockDim.x + threadIdx.x) >> 5;
    int lane = threadIdx.x & 31;
    if (gw >= NM*NQ) return;
    float x = (lane < NS) ? emis[(size_t)gw * NS + lane] : -3.4e38f;
    float v = x;
    #pragma unroll
    for (int o = 16; o; o >>= 1) v = fmaxf(v, __shfl_xor_sync(0xffffffffu, v, o));
    float mx = v;
    float e = (lane < NS) ? expf(x - mx) : 0.0f;
    v = e;
    #pragma unroll
    for (int o = 16; o; o >>= 1) v += __shfl_xor_sync(0xffffffffu, v, o);
    if (lane < NS) {
        int m = gw >> 9, q = gw & 511;
        g_Bt[((size_t)m * NS + lane) * NQ + q] = e / v;
    }
}

// ============================================================
// E = inputs @ B^T + eps.
// ============================================================
__global__ void em_kernel(const float* __restrict__ inp) {
    __shared__ float srow[NS];
    int t = threadIdx.x;
    int row0 = blockIdx.x * 16;
    int m = row0 / (NB*NL);
    const float* __restrict__ Bt = g_Bt + (size_t)m * NS * NQ;
    for (int r = 0; r < 16; r++) {
        int row = row0 + r;
        __syncthreads();
        if (t < NS) srow[t] = inp[(size_t)row * NS + t];
        __syncthreads();
        float acc = HMM_EPS;
        #pragma unroll
        for (int s = 0; s < NS; s++)
            acc = fmaf(srow[s], __ldg(&Bt[s * NQ + t]), acc);
        g_E[(size_t)row * NQ + t] = acc;
    }
}

// ============================================================
// Fused forward/backward scaled recursions, bf16 A, f32x2 math.
// 32 CTAs: dir(2) x model(2) x batch-quad(8). 512 threads:
//   matvec phase : (qoct = t&63) owns 8 q cols, (ks = t>>6) owns 64 k rows
//   reduce phase : thread t owns column q = t
// G=4 batches share every A load + bf16 expansion.
// Dynamic smem: vq01,vq23 (dup state), partA/partB (k-split partials).
// ============================================================
__global__ void __launch_bounds__(512, 1) fb_kernel() {
    extern __shared__ __align__(16) unsigned char smem_raw[];
    float4* vq01  = (float4*)smem_raw;             // [NQ] (v0,v0,v1,v1)
    float4* vq23  = vq01 + NQ;                     // [NQ] (v2,v2,v3,v3)
    float2* partA = (float2*)(vq23 + NQ);          // [8][NQ] (b0,b1)
    float2* partB = partA + 8*NQ;                  // [8][NQ] (b2,b3)
    float4* red4  = (float4*)(partB + 8*NQ);       // [16]

    int bx  = blockIdx.x;
    int dir = bx >> 4;
    int m   = (bx >> 3) & 1;
    int pr  = bx & 7;
    int t   = threadIdx.x;
    int qoct = t & 63;          // matvec: q-octet
    int ks   = t >> 6;          // matvec: k-slice 0..7
    int q    = t;               // reduce: owned column
    int lane = t & 31;

    const __nv_bfloat16* __restrict__ Abase =
        (dir == 0 ? g_Ah : g_ATh) + (size_t)m * NQ * NQ;
    const uint4* __restrict__ Ap0 =
        (const uint4*)(Abase + (size_t)(ks * 64) * NQ + qoct * 8);

    float* stv = (dir == 0 ? g_alpha : g_beta);
    float* Ss  = (dir == 0 ? g_Sa    : g_Sb);

    size_t rr = (size_t)(m * NB + pr * 4) * NL;    // batches b0..b3 consecutive
    float* out0 = stv + (rr           ) * NQ;
    float* out1 = stv + (rr +     NL  ) * NQ;
    float* out2 = stv + (rr + 2 * NL  ) * NQ;
    float* out3 = stv + (rr + 3 * NL  ) * NQ;
    const float* __restrict__ E0 = g_E + (rr          ) * NQ;
    const float* __restrict__ E1 = g_E + (rr +     NL ) * NQ;
    const float* __restrict__ E2 = g_E + (rr + 2 * NL ) * NQ;
    const float* __restrict__ E3 = g_E + (rr + 3 * NL ) * NQ;
    float* S0p = Ss + rr;
    float* S1p = Ss + rr + NL;
    float* S2p = Ss + rr + 2 * NL;
    float* S3p = Ss + rr + 3 * NL;

    uint32_t vq01_addr = smem_u32(vq01 + ks * 64);
    uint32_t vq23_addr = smem_u32(vq23 + ks * 64);

    float S0 = 0.f, S1 = 0.f, S2 = 0.f, S3 = 0.f;  // live in thread 0 only

    // ---- matvec over vq into partials; leaves partA/partB filled ----
    auto matvec = [&]() {
        ull a0[4] = {0,0,0,0};   // batch0, q-pairs
        ull a1[4] = {0,0,0,0};
        ull a2[4] = {0,0,0,0};
        ull a3[4] = {0,0,0,0};
        const uint4* __restrict__ ap = Ap0;
        #pragma unroll 4
        for (int k = 0; k < 64; k++) {
            ull y0, y1, y2, y3;
            lds_y(vq01_addr + k * 16, y0, y1);
            lds_y(vq23_addr + k * 16, y2, y3);
            uint4 w = __ldg(ap); ap += 64;   // next k row (512 bf16)
            ull x0 = bf2f2(w.x), x1 = bf2f2(w.y), x2 = bf2f2(w.z), x3 = bf2f2(w.w);
            FMA2(a0[0], x0, y0); FMA2(a0[1], x1, y0);
            FMA2(a0[2], x2, y0); FMA2(a0[3], x3, y0);
            FMA2(a1[0], x0, y1); FMA2(a1[1], x1, y1);
            FMA2(a1[2], x2, y1); FMA2(a1[3], x3, y1);
            FMA2(a2[0], x0, y2); FMA2(a2[1], x1, y2);
            FMA2(a2[2], x2, y2); FMA2(a2[3], x3, y2);
            FMA2(a3[0], x0, y3); FMA2(a3[1], x1, y3);
            FMA2(a3[2], x2, y3); FMA2(a3[3], x3, y3);
        }
        #pragma unroll
        for (int j = 0; j < 4; j++) {
            float2 p0 = lohi(a0[j]);   // (w_{qp,b0}, w_{qp+1,b0})
            float2 p1 = lohi(a1[j]);
            float2 p2 = lohi(a2[j]);
            float2 p3 = lohi(a3[j]);
            int qp = (qoct << 3) + (j << 1);
            *(float4*)&partA[ks * NQ + qp] = make_float4(p0.x, p1.x, p0.y, p1.y);
            *(float4*)&partB[ks * NQ + qp] = make_float4(p2.x, p3.x, p2.y, p3.y);
        }
        __syncthreads();                 // partials visible
    };

    // ---- sum k-split partials for owned column q ----
    auto gather = [&]() {
        float4 w = make_float4(0.f, 0.f, 0.f, 0.f);
        #pragma unroll
        for (int s = 0; s < 8; s++) {
            float2 pa = partA[s * NQ + q];
            float2 pb = partB[s * NQ + q];
            w.x += pa.x; w.y += pa.y; w.z += pb.x; w.w += pb.y;
        }
        return w;
    };

    // ---- normalize w, store outputs, set vq for next step ----
    // uE: multiplier applied to n when writing vq (bwd E-fold); 1 for fwd
    auto finish = [&](float4 w, int l, float4 uE) {
        float s0 = w.x, s1 = w.y, s2 = w.z, s3 = w.w;
        #pragma unroll
        for (int o = 16; o; o >>= 1) {
            s0 += __shfl_xor_sync(0xffffffffu, s0, o);
            s1 += __shfl_xor_sync(0xffffffffu, s1, o);
            s2 += __shfl_xor_sync(0xffffffffu, s2, o);
            s3 += __shfl_xor_sync(0xffffffffu, s3, o);
        }
        if (lane == 0) red4[t >> 5] = make_float4(s0, s1, s2, s3);
        __syncthreads();
        float c0 = 0.f, c1 = 0.f, c2 = 0.f, c3 = 0.f;
        #pragma unroll
        for (int i = 0; i < 16; i++) {
            float4 r = red4[i];
            c0 += r.x; c1 += r.y; c2 += r.z; c3 += r.w;
        }
        if (t == 0) {
            S0 += __logf(c0); S1 += __logf(c1);
            S2 += __logf(c2); S3 += __logf(c3);
            S0p[l] = S0; S1p[l] = S1; S2p[l] = S2; S3p[l] = S3;
        }
        float n0 = w.x * __fdividef(1.f, c0);
        float n1 = w.y * __fdividef(1.f, c1);
        float n2 = w.z * __fdividef(1.f, c2);
        float n3 = w.w * __fdividef(1.f, c3);
        size_t o = (size_t)l * NQ + q;
        out0[o] = n0; out1[o] = n1; out2[o] = n2; out3[o] = n3;
        float u0 = n0 * uE.x, u1 = n1 * uE.y, u2 = n2 * uE.z, u3 = n3 * uE.w;
        vq01[q] = make_float4(u0, u0, u1, u1);
        vq23[q] = make_float4(u2, u2, u3, u3);
        __syncthreads();                 // vq ready for next matvec
    };

    float4 ones = make_float4(1.f, 1.f, 1.f, 1.f);

    if (dir == 0) {
        // ---- forward: alpha_0 = init * E_0 ----
        {
            float ini = g_init[m * NQ + q];
            float4 w = make_float4(ini * E0[q], ini * E1[q],
                                   ini * E2[q], ini * E3[q]);
            finish(w, 0, ones);
        }
        for (int l = 1; l < NL; l++) {
            matvec();
            size_t o = (size_t)l * NQ + q;
            float4 w = gather();
            w.x *= E0[o]; w.y *= E1[o]; w.z *= E2[o]; w.w *= E3[o];
            finish(w, l, ones);
        }
    } else {
        // ---- backward: beta_{L-1} = 1 ----
        {
            size_t o = (size_t)(NL - 1) * NQ + q;
            out0[o] = 1.f; out1[o] = 1.f; out2[o] = 1.f; out3[o] = 1.f;
            if (t == 0) { S0p[NL-1] = 0.f; S1p[NL-1] = 0.f;
                          S2p[NL-1] = 0.f; S3p[NL-1] = 0.f; }
            float e0 = E0[o], e1 = E1[o], e2 = E2[o], e3 = E3[o];
            vq01[q] = make_float4(e0, e0, e1, e1);
            vq23[q] = make_float4(e2, e2, e3, e3);
            __syncthreads();
        }
        for (int l = NL - 2; l >= 0; l--) {
            matvec();
            size_t o = (size_t)l * NQ + q;
            float4 uE = make_float4(E0[o], E1[o], E2[o], E3[o]);
            float4 w = gather();
            finish(w, l, uE);
        }
    }
}

#define FB_SMEM ((2*NQ)*16 + (16*NQ)*8 + 16*16)   // vq(16KB)+part(64KB)+red(256B)

// ============================================================
// posterior = log(alpha) + log(beta) + Sa + Sb - loglik
// ============================================================
__global__ void post_kernel(float* __restrict__ out) {
    int i = blockIdx.x * NQ + threadIdx.x;     // < NTOT
    int row = i >> 9;                          // (m,b,l)
    int mb  = row >> 9;                        // (m,b)
    float ll = g_Sa[mb * NL + (NL - 1)];
    out[i] = __logf(g_alpha[i]) + __logf(g_beta[i]) + g_Sa[row] + g_Sb[row] - ll;
    if (i < NM*NB) out[NTOT + i] = g_Sa[i * NL + (NL - 1)];
}

extern "C" void kernel_launch(void* const* d_in, const int* in_sizes, int n_in,
                              void* d_out, int out_size) {
    const float* inputs = (const float*)d_in[0];   // (2,32,512,26)
    const float* trans  = (const float*)d_in[1];   // (2,512,512)
    const float* emis   = (const float*)d_in[2];   // (2,512,26)
    const float* initl  = (const float*)d_in[3];   // (2,512)
    float* out = (float*)d_out;                    // posterior ++ loglik

    // host-side attribute set (idempotent, not a stream op — capture-safe)
    cudaFuncSetAttribute(fb_kernel,
                         cudaFuncAttributeMaxDynamicSharedMemorySize, FB_SMEM);

    prep_rows_kernel<<<NM*NQ + NM, NQ>>>(trans, initl);
    prep_B_kernel<<<(NM*NQ*32 + 255)/256, 256>>>(emis);
    em_kernel<<<NM*NB*NL/16, NQ>>>(inputs);
    fb_kernel<<<32, NQ, FB_SMEM>>>();
    post_kernel<<<NTOT/NQ, NQ>>>(out);
}

// round 17
// speedup vs baseline: 1.4871x; 1.4871x over previous
#include <cuda_runtime.h>
#include <cuda_bf16.h>
#include <math.h>
#include <stdint.h>

#define NM 2
#define NB 32
#define NL 512
#define NS 26
#define NQ 512
#define HMM_EPS 1e-16f
#define NTOT (NM*NB*NL*NQ)   // 16,777,216

typedef unsigned long long ull;
typedef uint32_t u32;

// ---- scratch (no allocs allowed: __device__ globals) ----
__device__ __nv_bfloat16 g_Ah [NM*NQ*NQ]; // [m][k][q] = A_hmm[k->q]
__device__ __nv_bfloat16 g_ATh[NM*NQ*NQ]; // [m][q][k] = A_hmm[k->q]
__device__ float  g_Bt[NM*NS*NQ];
__device__ float  g_init[NM*NQ];
__device__ float  g_E    [NTOT];          // em + eps, [m][b][l][q]
__device__ float  g_alpha[NTOT];
__device__ float  g_beta [NTOT];
__device__ float  g_Sa[NM*NB*NL];
__device__ float  g_Sb[NM*NB*NL];
// per-cluster exchange buffers (global, cluster-barrier ordered)
__device__ __align__(16) __nv_bfloat16 g_vx[4][32*NQ];  // [cid][b][k]
__device__ float g_cx[4][4][32];                        // [cid][rank][b]

// ================= PTX helpers (sm_90 baseline only) ====
__device__ __forceinline__ u32 smem_u32(const void* p) {
    u32 a;
    asm("{ .reg .u64 t; cvta.to.shared.u64 t, %1; cvt.u32.u64 %0, t; }"
        : "=r"(a) : "l"(p));
    return a;
}
// fence + cluster barrier: release/acquire orders our global writes
#define CLUSTER_SYNC() do { \
    asm volatile("fence.acq_rel.cluster;" ::: "memory"); \
    asm volatile("barrier.cluster.arrive.aligned;" ::: "memory"); \
    asm volatile("barrier.cluster.wait.aligned;" ::: "memory"); } while (0)

// ldmatrix x4: four 8x8 b16 tiles; lanes 8j..8j+7 address tile j's rows
__device__ __forceinline__ void ldsm4(u32& r0, u32& r1, u32& r2, u32& r3,
                                      u32 addr) {
    asm volatile("ldmatrix.sync.aligned.m8n8.x4.shared.b16 {%0,%1,%2,%3}, [%4];"
        : "=r"(r0), "=r"(r1), "=r"(r2), "=r"(r3) : "r"(addr));
}
// HMMA m16n8k16 bf16 -> f32 accumulate in place
__device__ __forceinline__ void hmma(float d[4], u32 a0, u32 a1, u32 a2, u32 a3,
                                     u32 b0, u32 b1) {
    asm volatile(
        "mma.sync.aligned.m16n8k16.row.col.f32.bf16.bf16.f32 "
        "{%0,%1,%2,%3}, {%4,%5,%6,%7}, {%8,%9}, {%0,%1,%2,%3};"
        : "+f"(d[0]), "+f"(d[1]), "+f"(d[2]), "+f"(d[3])
        : "r"(a0), "r"(a1), "r"(a2), "r"(a3), "r"(b0), "r"(b1));
}

// ---- smem layout. A/V rows padded to 1040B: conflict-free ldmatrix phases.
#define ASTRIDE 1040
#define WSTRIDE 144
#define SM_WARPC 0                         // float[4][32]
#define SM_CFIN  512                       // float[32]
#define SM_V     640                       // [32 b][520 bf16] = 33,280 B
#define SM_W     (SM_V + 32*ASTRIDE)       // [128 q][36 f32]  = 18,432 B
#define SM_A     (SM_W + 128*WSTRIDE)      // [128 q][520 bf16]= 133,120 B
#define FB_SMEM  (SM_A + 128*ASTRIDE)      // 185,472 B

// ============================================================
// Prep kernels (proven in R2-R6)
// ============================================================
__global__ void prep_rows_kernel(const float* __restrict__ trans,
                                 const float* __restrict__ initl) {
    int bid = blockIdx.x;
    int t = threadIdx.x;
    int lane = t & 31, warp = t >> 5;
    __shared__ float red[16];
    __shared__ float s_max, s_inv;

    const float* row;
    if (bid < NM*NQ) row = trans + (size_t)bid * NQ;
    else             row = initl + (size_t)(bid - NM*NQ) * NQ;
    float x = row[t];

    float v = x;
    #pragma unroll
    for (int o = 16; o; o >>= 1) v = fmaxf(v, __shfl_xor_sync(0xffffffffu, v, o));
    if (lane == 0) red[warp] = v;
    __syncthreads();
    if (t == 0) {
        float mm = red[0];
        #pragma unroll
        for (int i = 1; i < 16; i++) mm = fmaxf(mm, red[i]);
        s_max = mm;
    }
    __syncthreads();
    float e = expf(x - s_max);
    v = e;
    #pragma unroll
    for (int o = 16; o; o >>= 1) v += __shfl_xor_sync(0xffffffffu, v, o);
    if (lane == 0) red[warp] = v;
    __syncthreads();
    if (t == 0) {
        float s = 0.f;
        #pragma unroll
        for (int i = 0; i < 16; i++) s += red[i];
        s_inv = 1.0f / s;
    }
    __syncthreads();
    float p = e * s_inv;
    if (bid < NM*NQ) {
        int mi = bid >> 9, r = bid & 511;
        __nv_bfloat16 h = __float2bfloat16(p);
        g_Ah [(size_t)bid * NQ + t] = h;                 // [m][k=r][q=t]
        g_ATh[((size_t)mi * NQ + t) * NQ + r] = h;       // [m][q=t][k=r]
    } else {
        g_init[(bid - NM*NQ) * NQ + t] = p;
    }
}

__global__ void prep_B_kernel(const float* __restrict__ emis) {
    int gw = (blockIdx.x * blockDim.x + threadIdx.x) >> 5;
    int lane = threadIdx.x & 31;
    if (gw >= NM*NQ) return;
    float x = (lane < NS) ? emis[(size_t)gw * NS + lane] : -3.4e38f;
    float v = x;
    #pragma unroll
    for (int o = 16; o; o >>= 1) v = fmaxf(v, __shfl_xor_sync(0xffffffffu, v, o));
    float mx = v;
    float e = (lane < NS) ? expf(x - mx) : 0.0f;
    v = e;
    #pragma unroll
    for (int o = 16; o; o >>= 1) v += __shfl_xor_sync(0xffffffffu, v, o);
    if (lane < NS) {
        int mi = gw >> 9, q = gw & 511;
        g_Bt[((size_t)mi * NS + lane) * NQ + q] = e / v;
    }
}

__global__ void em_kernel(const float* __restrict__ inp) {
    __shared__ float srow[NS];
    int t = threadIdx.x;
    int row0 = blockIdx.x * 16;
    int mi = row0 / (NB*NL);
    const float* __restrict__ Bt = g_Bt + (size_t)mi * NS * NQ;
    for (int r = 0; r < 16; r++) {
        int row = row0 + r;
        __syncthreads();
        if (t < NS) srow[t] = inp[(size_t)row * NS + t];
        __syncthreads();
        float acc = HMM_EPS;
        #pragma unroll
        for (int s = 0; s < NS; s++)
            acc = fmaf(srow[s], __ldg(&Bt[s * NQ + t]), acc);
        g_E[(size_t)row * NQ + t] = acc;
    }
}

// ============================================================
// fb: HMMA recursion. 4 clusters (dir x m) x 4 CTAs (128-row
// M-slices), 128 threads. Per step: D[128,32]=A_slice*v^T via
// mma.sync, normalize, v_next exchanged through GLOBAL buffers
// ordered by fenced cluster barriers.
// ============================================================
__global__ void __launch_bounds__(128, 1) __cluster_dims__(4, 1, 1)
fb_kernel() {
    extern __shared__ __align__(16) unsigned char smraw[];
    u32 sm = smem_u32(smraw);

    int cid  = blockIdx.x >> 2;          // 0..3 = (dir, m)
    int rank = blockIdx.x & 3;           // M-slice rank
    int dir  = cid >> 1;
    int m    = cid & 1;
    int tid  = threadIdx.x;              // 0..127
    int wid  = tid >> 5;
    int lane = tid & 31;
    int gq   = rank * 128 + tid;         // owned global state index

    // ---- load A slice into padded smem rows (FULL 512-col row = 64 uint4) ----
    // fwd: Amma[q][k] = A_hmm[k->q] = g_ATh[m][q][k]  (row-contiguous)
    // bwd: Amma[j][k] = A_hmm[j->k] = g_Ah [m][j][k]  (row-contiguous)
    {
        const __nv_bfloat16* src =
            (dir ? g_Ah : g_ATh) + ((size_t)m * NQ + gq) * NQ;
        const uint4* s4 = (const uint4*)src;
        uint4* drow = (uint4*)(smraw + SM_A + tid * ASTRIDE);
        #pragma unroll
        for (int c = 0; c < 64; c++) drow[c] = __ldg(s4 + c);
    }

    float* stv = dir ? g_beta : g_alpha;
    float* Ss  = dir ? g_Sb   : g_Sa;
    const size_t BSTRIDE = (size_t)NL * NQ;

    float Sacc = 0.f;                    // meaningful for tid<32 only
    float* warpc = (float*)(smraw + SM_WARPC);
    float* cfin  = (float*)(smraw + SM_CFIN);
    const uint4* vx4 = (const uint4*)g_vx[cid];

    // per-warp ldmatrix base addresses
    u32 vbase = sm + SM_V + (u32)(lane & 7) * ASTRIDE + (u32)((lane >> 3) << 4);
    u32 abase = sm + SM_A + (u32)(wid * 32 + (lane & 15)) * ASTRIDE
                          + (u32)((lane >> 4) << 4);

    for (int i = 0; i < NL; i++) {
        int l = dir ? (NL - 1 - i) : i;

        float wv[32];
        if (i > 0) {
            // ---- copy v (g_vx, published by prev step's barrier) -> SM_V ----
            #pragma unroll
            for (int j = 0; j < 16; j++) {
                int ii = tid + j * 128;          // 2048 uint4 total
                int b = ii >> 6, c = ii & 63;
                *(uint4*)(smraw + SM_V + b * ASTRIDE + c * 16) = vx4[ii];
            }
            __syncthreads();

            // ---- MMA: D[128,32] = A_slice * v^T ----
            float d[2][4][4];
            #pragma unroll
            for (int mt = 0; mt < 2; mt++)
                #pragma unroll
                for (int nt = 0; nt < 4; nt++)
                    #pragma unroll
                    for (int j = 0; j < 4; j++) d[mt][nt][j] = 0.f;

            #pragma unroll 4
            for (int kt2 = 0; kt2 < 16; kt2++) {
                u32 kb = (u32)kt2 * 64;          // 32 bf16 cols = 64 B
                u32 b[4][4];
                #pragma unroll
                for (int nt = 0; nt < 4; nt++)
                    ldsm4(b[nt][0], b[nt][1], b[nt][2], b[nt][3],
                          vbase + (u32)(nt * 8) * ASTRIDE + kb);
                u32 a[2][2][4];
                #pragma unroll
                for (int mt = 0; mt < 2; mt++)
                    #pragma unroll
                    for (int kk = 0; kk < 2; kk++)
                        ldsm4(a[mt][kk][0], a[mt][kk][1],
                              a[mt][kk][2], a[mt][kk][3],
                              abase + (u32)(mt * 16) * ASTRIDE + kb + (u32)kk * 32);
                #pragma unroll
                for (int kk = 0; kk < 2; kk++)
                    #pragma unroll
                    for (int mt = 0; mt < 2; mt++)
                        #pragma unroll
                        for (int nt = 0; nt < 4; nt++)
                            hmma(d[mt][nt],
                                 a[mt][kk][0], a[mt][kk][1],
                                 a[mt][kk][2], a[mt][kk][3],
                                 b[nt][2*kk], b[nt][2*kk + 1]);
            }
            // ---- stage D fragments to SM_W, unstage thread-owns-q ----
            {
                int g = lane >> 2, t2 = (lane & 3) << 1;
                #pragma unroll
                for (int mt = 0; mt < 2; mt++) {
                    int row = wid * 32 + mt * 16 + g;
                    #pragma unroll
                    for (int nt = 0; nt < 4; nt++) {
                        int col = nt * 8 + t2;
                        *(float2*)(smraw + SM_W + row * WSTRIDE + col * 4) =
                            make_float2(d[mt][nt][0], d[mt][nt][1]);
                        *(float2*)(smraw + SM_W + (row + 8) * WSTRIDE + col * 4) =
                            make_float2(d[mt][nt][2], d[mt][nt][3]);
                    }
                }
            }
            __syncthreads();
            #pragma unroll
            for (int j = 0; j < 8; j++) {
                float4 f = *(const float4*)(smraw + SM_W + tid * WSTRIDE + j * 16);
                wv[4*j] = f.x; wv[4*j+1] = f.y; wv[4*j+2] = f.z; wv[4*j+3] = f.w;
            }
        }

        // ---- E_l for owned q, all 32 batches ----
        const float* Ep = g_E + ((size_t)m * NB * NL + l) * NQ + gq;
        float e[32];
        #pragma unroll
        for (int b = 0; b < 32; b++) e[b] = __ldg(Ep + b * BSTRIDE);

        float w[32];
        if (i == 0) {
            if (!dir) {
                float ini = g_init[m * NQ + gq];
                #pragma unroll
                for (int b = 0; b < 32; b++) w[b] = ini * e[b];
            }
        } else {
            if (!dir) {
                #pragma unroll
                for (int b = 0; b < 32; b++) w[b] = wv[b] * e[b];
            } else {
                #pragma unroll
                for (int b = 0; b < 32; b++) w[b] = wv[b];
            }
        }

        float vn[32];
        if (dir && i == 0) {
            float* ob = stv + ((size_t)m * NB * NL + l) * NQ + gq;
            #pragma unroll
            for (int b = 0; b < 32; b++) { ob[b * BSTRIDE] = 1.f; vn[b] = e[b]; }
            if (rank == 0 && tid < 32) Ss[(m * NB + tid) * NL + l] = 0.f;
        } else {
            // c_b = sum over q of w : packed f32x2 butterfly within warp
            ull pk[16];
            #pragma unroll
            for (int j = 0; j < 16; j++)
                asm("mov.b64 %0, {%1,%2};" : "=l"(pk[j])
                    : "f"(w[2*j]), "f"(w[2*j+1]));
            #pragma unroll
            for (int o = 16; o; o >>= 1) {
                #pragma unroll
                for (int j = 0; j < 16; j++) {
                    ull t2 = __shfl_xor_sync(0xffffffffu, pk[j], o);
                    asm("add.rn.f32x2 %0, %0, %1;" : "+l"(pk[j]) : "l"(t2));
                }
            }
            if (lane == 0) {
                #pragma unroll
                for (int j = 0; j < 16; j++)
                    *(ull*)&warpc[wid * 32 + 2*j] = pk[j];
            }
            __syncthreads();
            if (tid < 32) {
                float cp = warpc[tid] + warpc[32 + tid] +
                           warpc[64 + tid] + warpc[96 + tid];
                g_cx[cid][rank][tid] = cp;       // publish partial (global)
            }
            CLUSTER_SYNC();                      // partials visible
            if (tid < 32) {
                float c = g_cx[cid][0][tid] + g_cx[cid][1][tid] +
                          g_cx[cid][2][tid] + g_cx[cid][3][tid];
                cfin[tid] = __fdividef(1.f, c);
                Sacc += __logf(c);
                if (rank == 0) Ss[(m * NB + tid) * NL + l] = Sacc;
            }
            __syncthreads();
            float inv[32];
            #pragma unroll
            for (int b = 0; b < 32; b++) inv[b] = cfin[b];
            float* ob = stv + ((size_t)m * NB * NL + l) * NQ + gq;
            #pragma unroll
            for (int b = 0; b < 32; b++) {
                float nb = w[b] * inv[b];
                ob[b * BSTRIDE] = nb;
                vn[b] = dir ? nb * e[b] : nb;    // bwd folds E_l into operand
            }
        }

        if (i != NL - 1) {
            // publish v_next[b][k] bf16 for this CTA's k-slice (global)
            float pr[32];
            #pragma unroll
            for (int b = 0; b < 32; b++)
                pr[b] = __shfl_xor_sync(0xffffffffu, vn[b], 1);
            int kp = gq & ~1;
            bool even = !(gq & 1);
            int bbase = even ? 0 : 16;
            #pragma unroll
            for (int j = 0; j < 16; j++) {
                int b = bbase + j;
                float lo = even ? vn[b] : pr[b];     // k = kp
                float hi = even ? pr[b] : vn[b];     // k = kp+1
                u32 packed;
                asm("cvt.rn.bf16x2.f32 %0, %1, %2;"
                    : "=r"(packed) : "f"(hi), "f"(lo));
                *(u32*)&g_vx[cid][b * NQ + kp] = packed;
            }
        }
        CLUSTER_SYNC();                              // v published cluster-wide
    }
}

// ============================================================
// posterior = log(alpha) + log(beta) + Sa + Sb - loglik
// ============================================================
__global__ void post_kernel(float* __restrict__ out) {
    int i = blockIdx.x * NQ + threadIdx.x;
    int row = i >> 9;
    int mb  = row >> 9;
    float ll = g_Sa[mb * NL + (NL - 1)];
    out[i] = __logf(g_alpha[i]) + __logf(g_beta[i]) + g_Sa[row] + g_Sb[row] - ll;
    if (i < NM*NB) out[NTOT + i] = g_Sa[i * NL + (NL - 1)];
}

extern "C" void kernel_launch(void* const* d_in, const int* in_sizes, int n_in,
                              void* d_out, int out_size) {
    const float* inputs = (const float*)d_in[0];   // (2,32,512,26)
    const float* trans  = (const float*)d_in[1];   // (2,512,512)
    const float* emis   = (const float*)d_in[2];   // (2,512,26)
    const float* initl  = (const float*)d_in[3];   // (2,512)
    float* out = (float*)d_out;                    // posterior ++ loglik

    cudaFuncSetAttribute(fb_kernel,
                         cudaFuncAttributeMaxDynamicSharedMemorySize, FB_SMEM);

    prep_rows_kernel<<<NM*NQ + NM, NQ>>>(trans, initl);
    prep_B_kernel<<<(NM*NQ*32 + 255)/256, 256>>>(emis);
    em_kernel<<<NM*NB*NL/16, NQ>>>(inputs);
    fb_kernel<<<16, 128, FB_SMEM>>>();
    post_kernel<<<NTOT/NQ, NQ>>>(out);
}